// round 2
// baseline (speedup 1.0000x reference)
#include <cuda_runtime.h>
#include <math.h>

// Problem constants (fixed shapes per reference: B=1024, D=1024, M=128)
#define MAX_B     1024
#define D_F4      256      // D=1024 floats = 256 float4
#define M_DOCS    128
#define TEMP_INV  50.0f    // 1/0.02

// Scratch (no device allocation allowed)
__device__ int   g_offsets[MAX_B];
__device__ float g_partial[MAX_B];

// Streaming load helper: evict-first, docs are touched exactly once.
__device__ __forceinline__ float4 ldg_cs(const float4* p) {
    float4 v;
    asm volatile("ld.global.cs.v4.f32 {%0,%1,%2,%3}, [%4];"
                 : "=f"(v.x), "=f"(v.y), "=f"(v.z), "=f"(v.w) : "l"(p));
    return v;
}

// ---------------------------------------------------------------------------
// Kernel 1: exclusive prefix sum of num_docs_per_sample -> g_offsets
// ---------------------------------------------------------------------------
__global__ __launch_bounds__(1024) void scan_offsets(const int* __restrict__ nd, int B) {
    __shared__ int s[1024];
    int t = threadIdx.x;
    int v = (t < B) ? nd[t] : 0;
    s[t] = v;
    __syncthreads();
    #pragma unroll
    for (int off = 1; off < 1024; off <<= 1) {
        int add = (t >= off) ? s[t - off] : 0;
        __syncthreads();
        s[t] += add;
        __syncthreads();
    }
    if (t < B) g_offsets[t] = s[t] - v;   // exclusive
}

// ---------------------------------------------------------------------------
// Kernel 2: one CTA per sample. 8 warps; each warp streams TWO doc rows per
// iteration (16 outstanding LDG.128 per lane), dots against smem query, then
// masked log-softmax + KL epilogue with deterministic block reductions.
// ---------------------------------------------------------------------------
__global__ __launch_bounds__(256) void distill_kernel(
    const float4* __restrict__ q,       // [B, 256] float4
    const float4* __restrict__ docs,    // [total, 256] float4
    const float*  __restrict__ labels,  // [B, 128]
    const int*    __restrict__ nd_arr)  // [B]
{
    const int b    = blockIdx.x;
    const int tid  = threadIdx.x;
    const int lane = tid & 31;
    const int wid  = tid >> 5;

    __shared__ float4 sq[D_F4];     // 4 KB query row
    __shared__ float  sims[M_DOCS];
    __shared__ float  sred[8];

    // Stage query row
    sq[tid] = q[(size_t)b * D_F4 + tid];
    const int nd  = nd_arr[b];
    const int off = g_offsets[b];
    __syncthreads();

    // Cache the query slice this lane always uses in registers.
    float4 qr[8];
    #pragma unroll
    for (int i = 0; i < 8; i++) qr[i] = sq[lane + 32 * i];

    // --- similarity scores: 2 doc rows per warp-iteration ---
    int m = wid * 2;
    const int step = 16;  // 8 warps * 2 rows
    for (; m + 1 < nd; m += step) {
        const float4* d0 = docs + (size_t)(off + m)     * D_F4;
        const float4* d1 = docs + (size_t)(off + m + 1) * D_F4;
        float a0 = 0.f, a1 = 0.f;
        #pragma unroll
        for (int i = 0; i < 8; i++) {
            float4 v0 = ldg_cs(d0 + lane + 32 * i);
            float4 v1 = ldg_cs(d1 + lane + 32 * i);
            float4 qv = qr[i];
            a0 = fmaf(v0.x, qv.x, a0); a1 = fmaf(v1.x, qv.x, a1);
            a0 = fmaf(v0.y, qv.y, a0); a1 = fmaf(v1.y, qv.y, a1);
            a0 = fmaf(v0.z, qv.z, a0); a1 = fmaf(v1.z, qv.z, a1);
            a0 = fmaf(v0.w, qv.w, a0); a1 = fmaf(v1.w, qv.w, a1);
        }
        #pragma unroll
        for (int s = 16; s; s >>= 1) {
            a0 += __shfl_xor_sync(0xffffffffu, a0, s);
            a1 += __shfl_xor_sync(0xffffffffu, a1, s);
        }
        if (lane == 0) { sims[m] = a0 * TEMP_INV; sims[m + 1] = a1 * TEMP_INV; }
    }
    if (m < nd) {  // odd tail row for this warp
        const float4* d0 = docs + (size_t)(off + m) * D_F4;
        float a0 = 0.f;
        #pragma unroll
        for (int i = 0; i < 8; i++) {
            float4 v0 = ldg_cs(d0 + lane + 32 * i);
            float4 qv = qr[i];
            a0 = fmaf(v0.x, qv.x, a0);
            a0 = fmaf(v0.y, qv.y, a0);
            a0 = fmaf(v0.z, qv.z, a0);
            a0 = fmaf(v0.w, qv.w, a0);
        }
        #pragma unroll
        for (int s = 16; s; s >>= 1) a0 += __shfl_xor_sync(0xffffffffu, a0, s);
        if (lane == 0) sims[m] = a0 * TEMP_INV;
    }
    __syncthreads();

    // --- masked log-softmax + KL (threads >= nd contribute identities) ---
    const bool act = (tid < nd);                 // nd <= 128 <= blockDim
    const float simv = act ? sims[tid] : 0.f;

    // 1) max
    float mv = act ? simv : -INFINITY;
    #pragma unroll
    for (int s = 16; s; s >>= 1) mv = fmaxf(mv, __shfl_xor_sync(0xffffffffu, mv, s));
    if (lane == 0) sred[wid] = mv;
    __syncthreads();
    float maxv = sred[0];
    #pragma unroll
    for (int i = 1; i < 8; i++) maxv = fmaxf(maxv, sred[i]);
    __syncthreads();

    // 2) sum of exp
    float e = act ? __expf(simv - maxv) : 0.f;
    float se = e;
    #pragma unroll
    for (int s = 16; s; s >>= 1) se += __shfl_xor_sync(0xffffffffu, se, s);
    if (lane == 0) sred[wid] = se;
    __syncthreads();
    float sumexp = 0.f;
    #pragma unroll
    for (int i = 0; i < 8; i++) sumexp += sred[i];
    __syncthreads();
    const float logZ = maxv + __logf(sumexp);

    // 3) teacher mass
    const float tl = act ? labels[(size_t)b * M_DOCS + tid] : 0.f;
    float ts = tl;
    #pragma unroll
    for (int s = 16; s; s >>= 1) ts += __shfl_xor_sync(0xffffffffu, ts, s);
    if (lane == 0) sred[wid] = ts;
    __syncthreads();
    float tsum = 0.f;
    #pragma unroll
    for (int i = 0; i < 8; i++) tsum += sred[i];
    __syncthreads();

    // 4) KL contribution
    const float tp = tl / (tsum + 1e-9f);
    float kl = 0.f;
    if (act && tp > 0.f) kl = tp * (__logf(tp) - (simv - logZ));
    #pragma unroll
    for (int s = 16; s; s >>= 1) kl += __shfl_xor_sync(0xffffffffu, kl, s);
    if (lane == 0) sred[wid] = kl;
    __syncthreads();
    if (tid == 0) {
        float tot = 0.f;
        #pragma unroll
        for (int i = 0; i < 8; i++) tot += sred[i];
        g_partial[b] = tot;
    }
}

// ---------------------------------------------------------------------------
// Kernel 3: reduce per-sample partials, divide by B, write scalar output.
// ---------------------------------------------------------------------------
__global__ __launch_bounds__(256) void final_reduce(float* __restrict__ out, int B) {
    __shared__ float sred[8];
    int tid = threadIdx.x;
    float s = 0.f;
    for (int i = tid; i < B; i += 256) s += g_partial[i];
    #pragma unroll
    for (int sh = 16; sh; sh >>= 1) s += __shfl_xor_sync(0xffffffffu, s, sh);
    if ((tid & 31) == 0) sred[tid >> 5] = s;
    __syncthreads();
    if (tid == 0) {
        float tot = 0.f;
        #pragma unroll
        for (int i = 0; i < 8; i++) tot += sred[i];
        out[0] = tot / (float)B;
    }
}

extern "C" void kernel_launch(void* const* d_in, const int* in_sizes, int n_in,
                              void* d_out, int out_size) {
    const float4* q      = (const float4*)d_in[0];   // query_embeds [B, D]
    const float4* docs   = (const float4*)d_in[1];   // doc_embeds [total, D]
    const float*  labels = (const float*) d_in[2];   // soft_labels [B, M]
    const int*    nd     = (const int*)   d_in[3];   // num_docs_per_sample [B]
    const int B = in_sizes[3];

    scan_offsets  <<<1, 1024>>>(nd, B);
    distill_kernel<<<B, 256>>>(q, docs, labels, nd);
    final_reduce  <<<1, 256>>>((float*)d_out, B);
}